// round 1
// baseline (speedup 1.0000x reference)
#include <cuda_runtime.h>
#include <math.h>

#define NN 50000
#define EE 800000

// ---------------- scratch (static device globals; no allocs) ----------------
__device__ float g_y1  [NN * 128];
__device__ float g_skip[NN * 128];
__device__ float g_agg1[NN * 128];
__device__ float g_y2  [NN * 128];
__device__ float g_agg2[NN * 128];
__device__ int   g_deg [NN];
__device__ int   g_off [NN + 1];
__device__ int   g_cur [NN];
__device__ int   g_csr [EE];
__device__ float g_stat[3 * 256];   // [inst]{sum[128], sumsq[128]}  inst: 0=skip,1=conv1,2=conv2
__device__ float g_bn  [3 * 256];   // [inst]{scale[128], shift[128]}

// ---------------- init ----------------
__global__ void k_init() {
    int i = blockIdx.x * 256 + threadIdx.x;
    if (i < NN)  g_deg[i]  = 0;
    if (i < 768) g_stat[i] = 0.0f;
}

// ---------------- CSR build ----------------
__global__ void k_hist(const int* __restrict__ ei) {
    int e = blockIdx.x * 256 + threadIdx.x;
    if (e < EE) atomicAdd(&g_deg[ei[EE + e]], 1);
}

__global__ void k_scan() {
    __shared__ int sh[1024];
    int carry = 0;
    for (int base = 0; base < NN; base += 1024) {
        int i = base + threadIdx.x;
        int v = (i < NN) ? g_deg[i] : 0;
        sh[threadIdx.x] = v;
        __syncthreads();
        for (int o = 1; o < 1024; o <<= 1) {
            int t = (threadIdx.x >= o) ? sh[threadIdx.x - o] : 0;
            __syncthreads();
            sh[threadIdx.x] += t;
            __syncthreads();
        }
        if (i < NN) {
            int ex = sh[threadIdx.x] - v + carry;
            g_off[i] = ex;
            g_cur[i] = ex;
        }
        carry += sh[1023];
        __syncthreads();
    }
    if (threadIdx.x == 0) g_off[NN] = carry;
}

__global__ void k_scatter(const int* __restrict__ ei) {
    int e = blockIdx.x * 256 + threadIdx.x;
    if (e < EE) {
        int s = ei[e];
        int d = ei[EE + e];
        int p = atomicAdd(&g_cur[d], 1);
        g_csr[p] = s;
    }
}

// ---------------- GEMM1: y1 = x@W1[0:64] + b1  AND  skip = x@Wl + bl ----------------
// M tile 64, 256 output cols (y1|skip), K=64 in 2 chunks of 32. 256 threads, 8x8 micro-tile.
__global__ __launch_bounds__(256) void k_gemm1(const float* __restrict__ x,
                                               const float* __restrict__ W1,
                                               const float* __restrict__ b1,
                                               const float* __restrict__ Wl,
                                               const float* __restrict__ bl) {
    __shared__ float Xs[64][36];
    __shared__ float Wc[32][256];
    int t  = threadIdx.x;
    int m0 = blockIdx.x * 64;
    int tr = t >> 5;   // 0..7
    int tc = t & 31;   // 0..31
    float acc[8][8];
#pragma unroll
    for (int i = 0; i < 8; i++)
#pragma unroll
        for (int j = 0; j < 8; j++) acc[i][j] = 0.0f;

    for (int kb = 0; kb < 64; kb += 32) {
        // load X tile (64 x 32)
        {
            int r  = t >> 2;
            int c0 = (t & 3) * 8;
            int row = m0 + r;
            float4 v0 = make_float4(0, 0, 0, 0), v1 = v0;
            if (row < NN) {
                const float4* p = (const float4*)(x + row * 64 + kb + c0);
                v0 = p[0];
                v1 = p[1];
            }
            *(float4*)&Xs[r][c0]     = v0;
            *(float4*)&Xs[r][c0 + 4] = v1;
        }
        // load combined W tile (32 x 256)
        {
            int k   = t >> 3;
            int c0w = (t & 7) * 32;
#pragma unroll
            for (int j = 0; j < 32; j += 4) {
                int c = c0w + j;
                float4 w;
                if (c < 128) w = *(const float4*)(W1 + (kb + k) * 128 + c);
                else         w = *(const float4*)(Wl + (kb + k) * 128 + (c - 128));
                *(float4*)&Wc[k][c] = w;
            }
        }
        __syncthreads();
#pragma unroll
        for (int k2 = 0; k2 < 32; k2++) {
            float a[8];
#pragma unroll
            for (int i = 0; i < 8; i++) a[i] = Xs[tr * 8 + i][k2];
            float4 bv0 = *(float4*)&Wc[k2][tc * 8];
            float4 bv1 = *(float4*)&Wc[k2][tc * 8 + 4];
            float b[8] = {bv0.x, bv0.y, bv0.z, bv0.w, bv1.x, bv1.y, bv1.z, bv1.w};
#pragma unroll
            for (int i = 0; i < 8; i++)
#pragma unroll
                for (int j = 0; j < 8; j++) acc[i][j] = fmaf(a[i], b[j], acc[i][j]);
        }
        __syncthreads();
    }
    // epilogue (+bias). Each 8-col chunk lives entirely in y1 or skip.
    int c0 = tc * 8;
    float bias[8];
#pragma unroll
    for (int j = 0; j < 8; j++) {
        int c = c0 + j;
        bias[j] = (c < 128) ? b1[c] : bl[c - 128];
    }
#pragma unroll
    for (int i = 0; i < 8; i++) {
        int row = m0 + tr * 8 + i;
        if (row >= NN) continue;
        float4 o0, o1;
        o0.x = acc[i][0] + bias[0]; o0.y = acc[i][1] + bias[1];
        o0.z = acc[i][2] + bias[2]; o0.w = acc[i][3] + bias[3];
        o1.x = acc[i][4] + bias[4]; o1.y = acc[i][5] + bias[5];
        o1.z = acc[i][6] + bias[6]; o1.w = acc[i][7] + bias[7];
        if (c0 < 128) {
            *(float4*)(g_y1 + row * 128 + c0)     = o0;
            *(float4*)(g_y1 + row * 128 + c0 + 4) = o1;
        } else {
            *(float4*)(g_skip + row * 128 + (c0 - 128))     = o0;
            *(float4*)(g_skip + row * 128 + (c0 - 128) + 4) = o1;
        }
    }
}

// ---------------- GEMM2: y2 = relu(BN1(agg1)) @ W2[0:128] + b2 ----------------
// M tile 128, N=128, K=128 in chunks of 32. 256 threads, 8x8 micro-tile.
__global__ __launch_bounds__(256) void k_gemm2(const float* __restrict__ W2,
                                               const float* __restrict__ b2) {
    __shared__ float Xs[128][36];
    __shared__ float Ws[32][128];
    __shared__ float sc[128], sf[128];
    int t = threadIdx.x;
    if (t < 128) {
        sc[t] = g_bn[256 + t];
        sf[t] = g_bn[256 + 128 + t];
    }
    int m0 = blockIdx.x * 128;
    int tr = t >> 4;   // 0..15
    int tc = t & 15;   // 0..15
    float acc[8][8];
#pragma unroll
    for (int i = 0; i < 8; i++)
#pragma unroll
        for (int j = 0; j < 8; j++) acc[i][j] = 0.0f;
    __syncthreads();

    for (int kb = 0; kb < 128; kb += 32) {
        // load agg1 tile with BN+relu applied (128 rows x 32 k)
        {
            int r  = t >> 1;
            int c0 = (t & 1) * 16;
            int row = m0 + r;
#pragma unroll
            for (int j = 0; j < 16; j += 4) {
                int kk = c0 + j;        // 0..31 local
                int kg = kb + kk;       // global feature
                float4 v = make_float4(0, 0, 0, 0);
                if (row < NN) v = *(const float4*)(g_agg1 + row * 128 + kg);
                v.x = fmaxf(fmaf(v.x, sc[kg],     sf[kg]),     0.0f);
                v.y = fmaxf(fmaf(v.y, sc[kg + 1], sf[kg + 1]), 0.0f);
                v.z = fmaxf(fmaf(v.z, sc[kg + 2], sf[kg + 2]), 0.0f);
                v.w = fmaxf(fmaf(v.w, sc[kg + 3], sf[kg + 3]), 0.0f);
                *(float4*)&Xs[r][kk] = v;
            }
        }
        // load W2 tile (32 x 128)
        {
            int kw = t >> 3;
            int cw = (t & 7) * 16;
#pragma unroll
            for (int j = 0; j < 16; j += 4)
                *(float4*)&Ws[kw][cw + j] = *(const float4*)(W2 + (kb + kw) * 128 + cw + j);
        }
        __syncthreads();
#pragma unroll
        for (int k2 = 0; k2 < 32; k2++) {
            float a[8];
#pragma unroll
            for (int i = 0; i < 8; i++) a[i] = Xs[tr * 8 + i][k2];
            float4 bv0 = *(float4*)&Ws[k2][tc * 8];
            float4 bv1 = *(float4*)&Ws[k2][tc * 8 + 4];
            float b[8] = {bv0.x, bv0.y, bv0.z, bv0.w, bv1.x, bv1.y, bv1.z, bv1.w};
#pragma unroll
            for (int i = 0; i < 8; i++)
#pragma unroll
                for (int j = 0; j < 8; j++) acc[i][j] = fmaf(a[i], b[j], acc[i][j]);
        }
        __syncthreads();
    }
    int c0 = tc * 8;
    float4 bb0 = *(const float4*)(b2 + c0);
    float4 bb1 = *(const float4*)(b2 + c0 + 4);
#pragma unroll
    for (int i = 0; i < 8; i++) {
        int row = m0 + tr * 8 + i;
        if (row >= NN) continue;
        float4 o0, o1;
        o0.x = acc[i][0] + bb0.x; o0.y = acc[i][1] + bb0.y;
        o0.z = acc[i][2] + bb0.z; o0.w = acc[i][3] + bb0.w;
        o1.x = acc[i][4] + bb1.x; o1.y = acc[i][5] + bb1.y;
        o1.z = acc[i][6] + bb1.z; o1.w = acc[i][7] + bb1.w;
        *(float4*)(g_y2 + row * 128 + c0)     = o0;
        *(float4*)(g_y2 + row * 128 + c0 + 4) = o1;
    }
}

// ---------------- aggregation: one warp per dst node, segment max ----------------
// msg = y[src] + rel @ Wp,  rel = pos[src] - pos[dst]
__global__ __launch_bounds__(256) void k_agg(const float* __restrict__ pos,
                                             const float* __restrict__ Wp,
                                             int phase) {
    int gw   = (blockIdx.x * 256 + threadIdx.x) >> 5;
    int lane = threadIdx.x & 31;
    if (gw >= NN) return;
    int f = lane * 4;
    float4 wx = *(const float4*)(Wp + f);
    float4 wy = *(const float4*)(Wp + 128 + f);
    float4 wz = *(const float4*)(Wp + 256 + f);
    const float* y = phase ? g_y2 : g_y1;
    float px = pos[gw * 3], py = pos[gw * 3 + 1], pz = pos[gw * 3 + 2];
    int e0 = g_off[gw], e1 = g_off[gw + 1];
    float ninf = __int_as_float(0xff800000);
    float4 acc = make_float4(ninf, ninf, ninf, ninf);
    for (int e = e0; e < e1; e++) {
        int s = g_csr[e];
        float rx = pos[s * 3]     - px;
        float ry = pos[s * 3 + 1] - py;
        float rz = pos[s * 3 + 2] - pz;
        float4 v = *(const float4*)(y + s * 128 + f);
        float4 m;
        m.x = fmaf(rz, wz.x, fmaf(ry, wy.x, fmaf(rx, wx.x, v.x)));
        m.y = fmaf(rz, wz.y, fmaf(ry, wy.y, fmaf(rx, wx.y, v.y)));
        m.z = fmaf(rz, wz.z, fmaf(ry, wy.z, fmaf(rx, wx.z, v.z)));
        m.w = fmaf(rz, wz.w, fmaf(ry, wy.w, fmaf(rx, wx.w, v.w)));
        acc.x = fmaxf(acc.x, m.x);
        acc.y = fmaxf(acc.y, m.y);
        acc.z = fmaxf(acc.z, m.z);
        acc.w = fmaxf(acc.w, m.w);
    }
    if (e0 == e1) acc = make_float4(0, 0, 0, 0);
    float* o = phase ? g_agg2 : g_agg1;
    *(float4*)(o + gw * 128 + f) = acc;
}

// ---------------- column stats (sum, sumsq per feature) ----------------
__global__ __launch_bounds__(256) void k_stats(int which) {
    const float* v = (which == 0) ? g_skip : ((which == 1) ? g_agg1 : g_agg2);
    float* st = g_stat + which * 256;
    int lane = threadIdx.x & 31;
    int w    = threadIdx.x >> 5;
    int gw   = blockIdx.x * 8 + w;
    int nw   = gridDim.x * 8;
    int f    = lane * 4;
    float4 s = make_float4(0, 0, 0, 0), q = s;
    for (int i = gw; i < NN; i += nw) {
        float4 x = *(const float4*)(v + i * 128 + f);
        s.x += x.x; s.y += x.y; s.z += x.z; s.w += x.w;
        q.x += x.x * x.x; q.y += x.y * x.y; q.z += x.z * x.z; q.w += x.w * x.w;
    }
    __shared__ float shs[8][128];
    __shared__ float shq[8][128];
    *(float4*)&shs[w][f] = s;
    *(float4*)&shq[w][f] = q;
    __syncthreads();
    if (threadIdx.x < 128) {
        float a = 0, b = 0;
#pragma unroll
        for (int w2 = 0; w2 < 8; w2++) {
            a += shs[w2][threadIdx.x];
            b += shq[w2][threadIdx.x];
        }
        atomicAdd(&st[threadIdx.x], a);
        atomicAdd(&st[128 + threadIdx.x], b);
    }
}

// ---------------- BN finalize: scale = g*rsqrt(var+eps), shift = beta - mu*scale ----------------
__global__ void k_finalize(const float* __restrict__ gamma,
                           const float* __restrict__ beta, int inst) {
    int f = threadIdx.x;
    float mu  = g_stat[inst * 256 + f] * (1.0f / NN);
    float var = g_stat[inst * 256 + 128 + f] * (1.0f / NN) - mu * mu;
    float rs  = rsqrtf(var + 1e-5f);
    float scale = gamma[f] * rs;
    g_bn[inst * 256 + f]       = scale;
    g_bn[inst * 256 + 128 + f] = beta[f] - mu * scale;
}

// ---------------- output: relu(BN2(agg2) + BNl(skip)) ----------------
__global__ __launch_bounds__(256) void k_out(float* __restrict__ out) {
    int tid = blockIdx.x * 256 + threadIdx.x;
    if (tid >= NN * 32) return;
    int i = tid >> 5;
    int f = (tid & 31) * 4;
    float4 a  = *(const float4*)(g_agg2 + i * 128 + f);
    float4 s  = *(const float4*)(g_skip + i * 128 + f);
    float4 c2 = *(const float4*)(g_bn + 512 + f);
    float4 h2 = *(const float4*)(g_bn + 512 + 128 + f);
    float4 cl = *(const float4*)(g_bn + f);
    float4 hl = *(const float4*)(g_bn + 128 + f);
    float4 o;
    o.x = fmaxf(fmaf(a.x, c2.x, h2.x) + fmaf(s.x, cl.x, hl.x), 0.0f);
    o.y = fmaxf(fmaf(a.y, c2.y, h2.y) + fmaf(s.y, cl.y, hl.y), 0.0f);
    o.z = fmaxf(fmaf(a.z, c2.z, h2.z) + fmaf(s.z, cl.z, hl.z), 0.0f);
    o.w = fmaxf(fmaf(a.w, c2.w, h2.w) + fmaf(s.w, cl.w, hl.w), 0.0f);
    *(float4*)(out + i * 128 + f) = o;
}

// ---------------- launcher ----------------
extern "C" void kernel_launch(void* const* d_in, const int* in_sizes, int n_in,
                              void* d_out, int out_size) {
    const float* x   = (const float*)d_in[0];
    const float* pos = (const float*)d_in[1];
    const int*   ei  = (const int*)  d_in[2];
    const float* W1  = (const float*)d_in[3];
    const float* b1  = (const float*)d_in[4];
    const float* g1  = (const float*)d_in[5];
    const float* be1 = (const float*)d_in[6];
    const float* W2  = (const float*)d_in[7];
    const float* b2  = (const float*)d_in[8];
    const float* g2  = (const float*)d_in[9];
    const float* be2 = (const float*)d_in[10];
    const float* Wl  = (const float*)d_in[11];
    const float* bl  = (const float*)d_in[12];
    const float* gl  = (const float*)d_in[13];
    const float* bel = (const float*)d_in[14];
    float* out = (float*)d_out;

    int gridE = (EE + 255) / 256;         // 3125
    int gridN = (NN + 255) / 256;         // 196
    int gridW = (NN * 32 + 255) / 256;    // 6250 (one warp per node)

    k_init<<<gridN, 256>>>();
    k_hist<<<gridE, 256>>>(ei);
    k_scan<<<1, 1024>>>();
    k_scatter<<<gridE, 256>>>(ei);

    // y1 = x@W1a + b1 ; skip = x@Wl + bl
    k_gemm1<<<(NN + 63) / 64, 256>>>(x, W1, b1, Wl, bl);
    k_stats<<<296, 256>>>(0);                       // skip stats

    // conv1 aggregation (Wp = last 3 rows of W1)
    k_agg<<<gridW, 256>>>(pos, W1 + 64 * 128, 0);
    k_stats<<<296, 256>>>(1);                       // agg1 stats
    k_finalize<<<1, 128>>>(gl, bel, 0);
    k_finalize<<<1, 128>>>(g1, be1, 1);

    // y2 = relu(BN1(agg1)) @ W2a + b2
    k_gemm2<<<(NN + 127) / 128, 256>>>(W2, b2);

    // conv2 aggregation (Wp = last 3 rows of W2)
    k_agg<<<gridW, 256>>>(pos, W2 + 128 * 128, 1);
    k_stats<<<296, 256>>>(2);
    k_finalize<<<1, 128>>>(g2, be2, 2);

    k_out<<<gridW, 256>>>(out);
}